// round 14
// baseline (speedup 1.0000x reference)
#include <cuda_runtime.h>
#include <cuda_bf16.h>
#include <cuda_fp16.h>
#include <cstdint>
#include <cstddef>

#define NPTS 8192
#define DIM  1024
typedef __nv_bfloat16 bf16;

#define AL __align__(256)
__device__ AL bf16 g_ph[(size_t)NPTS * DIM], g_pl[(size_t)NPTS * DIM];
__device__ AL bf16 g_rh[(size_t)NPTS * DIM], g_rl[(size_t)NPTS * DIM];
__device__ AL bf16 g_Whh[(size_t)DIM * DIM], g_Whl[(size_t)DIM * DIM];
__device__ AL bf16 g_Wlh[(size_t)DIM * DIM], g_Wll[(size_t)DIM * DIM];
__device__ AL bf16 g_Wgh[(size_t)DIM * DIM], g_Wgl[(size_t)DIM * DIM];
__device__ AL bf16 g_Qh[(size_t)NPTS * DIM], g_Ql[(size_t)NPTS * DIM];
__device__ AL bf16 g_Kh[(size_t)NPTS * DIM], g_Kl[(size_t)NPTS * DIM];
__device__ AL __half g_VT[(size_t)DIM * NPTS];
__device__ AL __half g_E[(size_t)NPTS * NPTS];
__device__ AL float g_M[64 * NPTS];
__device__ AL float g_S[64 * NPTS];
__device__ AL float g_sc[64 * NPTS];

__device__ __forceinline__ uint32_t smem_u32(const void* p) {
    uint32_t a;
    asm("{ .reg .u64 t; cvta.to.shared.u64 t, %1; cvt.u32.u64 %0, t; }" : "=r"(a) : "l"(p));
    return a;
}
__device__ __forceinline__ void cp16(uint32_t dst, const void* src) {
    asm volatile("cp.async.cg.shared.global [%0], [%1], 16;"
                 :: "r"(dst), "l"(__cvta_generic_to_global(src)) : "memory");
}
__device__ __forceinline__ void ldmx4(uint32_t* r, uint32_t addr) {
    asm volatile("ldmatrix.sync.aligned.m8n8.x4.shared.b16 {%0,%1,%2,%3}, [%4];"
                 : "=r"(r[0]), "=r"(r[1]), "=r"(r[2]), "=r"(r[3]) : "r"(addr));
}
__device__ __forceinline__ void mma_bf(float* c, const uint32_t* a, const uint32_t* b) {
    asm volatile("mma.sync.aligned.m16n8k16.row.col.f32.bf16.bf16.f32 "
                 "{%0,%1,%2,%3}, {%4,%5,%6,%7}, {%8,%9}, {%0,%1,%2,%3};"
                 : "+f"(c[0]), "+f"(c[1]), "+f"(c[2]), "+f"(c[3])
                 : "r"(a[0]), "r"(a[1]), "r"(a[2]), "r"(a[3]), "r"(b[0]), "r"(b[1]));
}
__device__ __forceinline__ void mma_hf(float* c, const uint32_t* a, const uint32_t* b) {
    asm volatile("mma.sync.aligned.m16n8k16.row.col.f32.f16.f16.f32 "
                 "{%0,%1,%2,%3}, {%4,%5,%6,%7}, {%8,%9}, {%0,%1,%2,%3};"
                 : "+f"(c[0]), "+f"(c[1]), "+f"(c[2]), "+f"(c[3])
                 : "r"(a[0]), "r"(a[1]), "r"(a[2]), "r"(a[3]), "r"(b[0]), "r"(b[1]));
}

// CTA tile 128x128, BK=32, cp.async pipeline (NSTGT stages). 4 warps, warp tile 64x64.
#define BK 32
#define GSMEM3 (3u * 32768u)
#define GSMEM1 (3u * 16384u)

__device__ __forceinline__ uint32_t swz(int row, int chunk) {
    return (uint32_t)(row * 64 + ((chunk ^ ((row >> 1) & 3)) << 4));
}

// MODE 0: bias+fp32 | 1: bias+bf16 hi/lo | 2: tile-softmax (fp16 E + M/S partials)
// MODE 3: residual fp32 | 4: bias + fp16 transposed (VT).  NPROD 3: hh+hl+lh | 1: hh.
template <int MODE, int NPROD, int HF, int NSTGT, int MINB>
__global__ __launch_bounds__(128, MINB) void gemm_mma(
    const bf16* __restrict__ Ahi, const bf16* __restrict__ Alo,
    const bf16* __restrict__ Bhi, const bf16* __restrict__ Blo,
    int Kd, int ldC, const float* __restrict__ bias, const float* __restrict__ P0,
    float* __restrict__ Cf, bf16* __restrict__ Chi, bf16* __restrict__ Clo,
    float* __restrict__ Mg, float* __restrict__ Sg)
{
    constexpr uint32_t STGB   = (NPROD == 1) ? 16384u : 32768u;
    constexpr uint32_t OF_ALO = 8192u;
    constexpr uint32_t OF_BHI = (NPROD == 1) ? 8192u : 16384u;
    constexpr uint32_t OF_BLO = 24576u;

    extern __shared__ char smraw[];
    const uint32_t sm0 = smem_u32(smraw);
    const int tid = threadIdx.x, lane = tid & 31, warp = tid >> 5;
    const int wm = warp >> 1, wn = warp & 1;           // 2x2 warp grid, 64x64 tiles
    const int row0 = blockIdx.y * 128, col0 = blockIdx.x * 128;

    uint32_t aoff[4][2], boff[4][2];
#pragma unroll
    for (int mi = 0; mi < 4; mi++)
#pragma unroll
        for (int ks = 0; ks < 2; ks++) {
            const int r = wm * 64 + mi * 16 + (lane & 15);
            aoff[mi][ks] = swz(r, ks * 2 + (lane >> 4));
        }
#pragma unroll
    for (int np = 0; np < 4; np++)
#pragma unroll
        for (int ks = 0; ks < 2; ks++) {
            const int r = wn * 64 + np * 16 + (lane & 7) + ((lane >> 4) & 1) * 8;
            boff[np][ks] = swz(r, ks * 2 + ((lane >> 3) & 1));
        }

    auto load_stage = [&](int kb, int st) {
        const int k0 = kb * BK;
        const uint32_t s = sm0 + (uint32_t)st * STGB;
#pragma unroll
        for (int i = 0; i < 4; i++) {
            const int id = i * 128 + tid;
            const int row = id >> 2, chunk = id & 3;
            const uint32_t d = swz(row, chunk);
            const size_t ga = (size_t)(row0 + row) * Kd + k0 + chunk * 8;
            const size_t gb = (size_t)(col0 + row) * Kd + k0 + chunk * 8;
            cp16(s + d, Ahi + ga);
            cp16(s + OF_BHI + d, Bhi + gb);
            if (NPROD == 3) {
                cp16(s + OF_ALO + d, Alo + ga);
                cp16(s + OF_BLO + d, Blo + gb);
            }
        }
    };

    float acc[4][8][4];
#pragma unroll
    for (int mi = 0; mi < 4; mi++)
#pragma unroll
        for (int ni = 0; ni < 8; ni++)
#pragma unroll
            for (int q = 0; q < 4; q++) acc[mi][ni][q] = 0.f;

    const int nkb = Kd / BK;
#pragma unroll
    for (int s = 0; s < NSTGT - 1; s++) {
        load_stage(s, s);
        asm volatile("cp.async.commit_group;" ::: "memory");
    }

    int st = 0, pf = NSTGT - 1;
    for (int kb = 0; kb < nkb; kb++) {
        asm volatile("cp.async.wait_group %0;" :: "n"(NSTGT - 2) : "memory");
        __syncthreads();
        if (kb + NSTGT - 1 < nkb) load_stage(kb + NSTGT - 1, pf);
        asm volatile("cp.async.commit_group;" ::: "memory");

        const uint32_t s = sm0 + (uint32_t)st * STGB;
#pragma unroll
        for (int ks = 0; ks < 2; ks++) {
            uint32_t ah[4][4], al[4][4], bh[8][2], bl[8][2];
#pragma unroll
            for (int mi = 0; mi < 4; mi++) {
                ldmx4(ah[mi], s + aoff[mi][ks]);
                if (NPROD == 3) ldmx4(al[mi], s + OF_ALO + aoff[mi][ks]);
            }
#pragma unroll
            for (int np = 0; np < 4; np++) {
                uint32_t t[4];
                ldmx4(t, s + OF_BHI + boff[np][ks]);
                bh[np*2][0] = t[0]; bh[np*2][1] = t[1];
                bh[np*2+1][0] = t[2]; bh[np*2+1][1] = t[3];
                if (NPROD == 3) {
                    ldmx4(t, s + OF_BLO + boff[np][ks]);
                    bl[np*2][0] = t[0]; bl[np*2][1] = t[1];
                    bl[np*2+1][0] = t[2]; bl[np*2+1][1] = t[3];
                }
            }
#pragma unroll
            for (int mi = 0; mi < 4; mi++)
#pragma unroll
                for (int ni = 0; ni < 8; ni++) {
                    if (HF) mma_hf(acc[mi][ni], ah[mi], bh[ni]);
                    else    mma_bf(acc[mi][ni], ah[mi], bh[ni]);
                }
            if (NPROD == 3) {
#pragma unroll
                for (int mi = 0; mi < 4; mi++)
#pragma unroll
                    for (int ni = 0; ni < 8; ni++)
                        mma_bf(acc[mi][ni], ah[mi], bl[ni]);
#pragma unroll
                for (int mi = 0; mi < 4; mi++)
#pragma unroll
                    for (int ni = 0; ni < 8; ni++)
                        mma_bf(acc[mi][ni], al[mi], bh[ni]);
            }
        }
        st = (st == NSTGT - 1) ? 0 : st + 1;
        pf = (pf == NSTGT - 1) ? 0 : pf + 1;
    }

    if (MODE == 2) {
        // Tile-local softmax epilogue; reuse stage smem (mainloop done).
        __syncthreads();
        float* Msm  = (float*)smraw;            // [2][128]
        float* Mfin = (float*)(smraw + 1024);   // [128]
        float* Ssm  = (float*)(smraw + 1536);   // [2][128]
#pragma unroll
        for (int ni = 0; ni < 8; ni++)
#pragma unroll
            for (int cc = 0; cc < 2; cc++) {
                float v = -1e30f;
#pragma unroll
                for (int mi = 0; mi < 4; mi++)
                    v = fmaxf(v, fmaxf(acc[mi][ni][cc], acc[mi][ni][2 + cc]));
                v = fmaxf(v, __shfl_xor_sync(0xffffffffu, v, 4));
                v = fmaxf(v, __shfl_xor_sync(0xffffffffu, v, 8));
                v = fmaxf(v, __shfl_xor_sync(0xffffffffu, v, 16));
                if (lane < 4) Msm[wm * 128 + wn * 64 + ni * 8 + lane * 2 + cc] = v;
            }
        __syncthreads();
        Mfin[tid] = fmaxf(Msm[tid], Msm[128 + tid]);
        __syncthreads();
        __half* Eo = (__half*)Chi;
        const float L2E = 1.4426950408889634f;
        float ss[8][2];
#pragma unroll
        for (int ni = 0; ni < 8; ni++) { ss[ni][0] = 0.f; ss[ni][1] = 0.f; }
#pragma unroll
        for (int mi = 0; mi < 4; mi++)
#pragma unroll
            for (int ni = 0; ni < 8; ni++) {
                const int cl = wn * 64 + ni * 8 + (lane & 3) * 2;
                const int c  = col0 + cl;
                const float M0 = Mfin[cl], M1 = Mfin[cl + 1];
#pragma unroll
                for (int h = 0; h < 2; h++) {
                    const int m = row0 + wm * 64 + mi * 16 + (lane >> 2) + h * 8;
                    float t0 = (acc[mi][ni][2 * h]     - M0) * L2E;
                    float t1 = (acc[mi][ni][2 * h + 1] - M1) * L2E;
                    __half2 ht = __floats2half2_rn(t0, t1);
                    uint32_t hin = *(uint32_t*)&ht, ho;
                    asm("ex2.approx.f16x2 %0, %1;" : "=r"(ho) : "r"(hin));
                    __half2 he = *(__half2*)&ho;
                    *(__half2*)&Eo[(size_t)m * ldC + c] = he;
                    float2 ef = __half22float2(he);
                    ss[ni][0] += ef.x; ss[ni][1] += ef.y;
                }
            }
#pragma unroll
        for (int ni = 0; ni < 8; ni++)
#pragma unroll
            for (int cc = 0; cc < 2; cc++) {
                float v = ss[ni][cc];
                v += __shfl_xor_sync(0xffffffffu, v, 4);
                v += __shfl_xor_sync(0xffffffffu, v, 8);
                v += __shfl_xor_sync(0xffffffffu, v, 16);
                if (lane < 4) Ssm[wm * 128 + wn * 64 + ni * 8 + lane * 2 + cc] = v;
            }
        __syncthreads();
        Mg[(size_t)blockIdx.y * ldC + col0 + tid] = Mfin[tid];
        Sg[(size_t)blockIdx.y * ldC + col0 + tid] = Ssm[tid] + Ssm[128 + tid];
        return;
    }

#pragma unroll
    for (int mi = 0; mi < 4; mi++)
#pragma unroll
        for (int ni = 0; ni < 8; ni++) {
            const int m0 = row0 + wm * 64 + mi * 16 + (lane >> 2);
            const int c  = col0 + wn * 64 + ni * 8 + (lane & 3) * 2;
#pragma unroll
            for (int h = 0; h < 2; h++) {
                const int m = m0 + h * 8;
                float v0 = acc[mi][ni][2 * h], v1 = acc[mi][ni][2 * h + 1];
                if (MODE == 0) {
                    float2* dst = (float2*)&Cf[(size_t)m * ldC + c];
                    *dst = make_float2(v0 + bias[c], v1 + bias[c + 1]);
                } else if (MODE == 3) {
                    const float2 pp = *(const float2*)&P0[(size_t)m * ldC + c];
                    float2* dst = (float2*)&Cf[(size_t)m * ldC + c];
                    *dst = make_float2(v0 + pp.x, v1 + pp.y);
                } else if (MODE == 4) {
                    __half* VTo = (__half*)Chi;
                    VTo[(size_t)c       * NPTS + m] = __float2half(v0 + bias[c]);
                    VTo[(size_t)(c + 1) * NPTS + m] = __float2half(v1 + bias[c + 1]);
                } else {  // MODE 1: bias + bf16 hi/lo split
                    v0 += bias[c]; v1 += bias[c + 1];
                    bf16 h0 = __float2bfloat16(v0), h1 = __float2bfloat16(v1);
                    *(__nv_bfloat162*)&Chi[(size_t)m * ldC + c] = __nv_bfloat162(h0, h1);
                    *(__nv_bfloat162*)&Clo[(size_t)m * ldC + c] =
                        __nv_bfloat162(__float2bfloat16(v0 - __bfloat162float(h0)),
                                       __float2bfloat16(v1 - __bfloat162float(h1)));
                }
            }
        }
}

// All five fp32->bf16 hi/lo splits in one launch (p, r, Wh, Wl, Wg).
__device__ __forceinline__ void split_one(const float4* x, __nv_bfloat162* hi,
                                          __nv_bfloat162* lo, int i) {
    float4 v = x[i];
    bf16 h0 = __float2bfloat16(v.x), h1 = __float2bfloat16(v.y);
    bf16 h2 = __float2bfloat16(v.z), h3 = __float2bfloat16(v.w);
    hi[2*i]   = __nv_bfloat162(h0, h1);
    hi[2*i+1] = __nv_bfloat162(h2, h3);
    lo[2*i]   = __nv_bfloat162(__float2bfloat16(v.x - __bfloat162float(h0)),
                               __float2bfloat16(v.y - __bfloat162float(h1)));
    lo[2*i+1] = __nv_bfloat162(__float2bfloat16(v.z - __bfloat162float(h2)),
                               __float2bfloat16(v.w - __bfloat162float(h3)));
}

__global__ __launch_bounds__(256) void split_all_kernel(
    const float4* p, __nv_bfloat162* ph, __nv_bfloat162* pl,
    const float4* r, __nv_bfloat162* rh, __nv_bfloat162* rl,
    const float4* wh, __nv_bfloat162* whh, __nv_bfloat162* whl,
    const float4* wl, __nv_bfloat162* wlh, __nv_bfloat162* wll,
    const float4* wg, __nv_bfloat162* wgh, __nv_bfloat162* wgl)
{
    const int nPD4 = NPTS * DIM / 4, nDD4 = DIM * DIM / 4;
    int i = blockIdx.x * 256 + threadIdx.x;
    if (i < nPD4) { split_one(p, ph, pl, i); return; }
    i -= nPD4;
    if (i < nPD4) { split_one(r, rh, rl, i); return; }
    i -= nPD4;
    if (i < nDD4) { split_one(wh, whh, whl, i); return; }
    i -= nDD4;
    if (i < nDD4) { split_one(wl, wlh, wll, i); return; }
    i -= nDD4;
    if (i < nDD4) split_one(wg, wgh, wgl, i);
}

// Combine 64 row-block partials -> per-column rescale factors sc[by][j]
__global__ __launch_bounds__(256) void merge_kernel(
    const float* __restrict__ Mg, const float* __restrict__ Sg, float* __restrict__ sc)
{
    const int j = blockIdx.x * 256 + threadIdx.x;
    float m = -1e30f;
#pragma unroll 8
    for (int by = 0; by < 64; by++) m = fmaxf(m, Mg[(size_t)by * NPTS + j]);
    float cs = 0.f;
#pragma unroll 8
    for (int by = 0; by < 64; by++)
        cs += Sg[(size_t)by * NPTS + j] * __expf(Mg[(size_t)by * NPTS + j] - m);
    const float rcv = 1.0f / cs;
#pragma unroll 8
    for (int by = 0; by < 64; by++)
        sc[(size_t)by * NPTS + j] = __expf(Mg[(size_t)by * NPTS + j] - m) * rcv;
}

// In-place: E[i,j] *= sc[i>>7][j]
__global__ __launch_bounds__(256) void norm_kernel(
    __half2* __restrict__ E, const float* __restrict__ sc)
{
    const int j2 = blockIdx.x * 256 + threadIdx.x;
    const int j = j2 * 2;
    const size_t i0 = (size_t)blockIdx.y * (NPTS / 16);
    for (int t = 0; t < NPTS / 16; t++) {
        const size_t i = i0 + t;
        const float* scr = sc + ((i >> 7) * (size_t)NPTS);
        const size_t idx = i * (NPTS / 2) + j2;
        float2 ef = __half22float2(E[idx]);
        E[idx] = __floats2half2_rn(ef.x * scr[j], ef.y * scr[j + 1]);
    }
}

extern "C" void kernel_launch(void* const* d_in, const int* in_sizes, int n_in,
                              void* d_out, int out_size)
{
    const float* p  = (const float*)d_in[0];
    const float* r  = (const float*)d_in[1];
    const float* Wh = (const float*)d_in[2];
    const float* bh = (const float*)d_in[3];
    const float* Wl = (const float*)d_in[4];
    const float* bl = (const float*)d_in[5];
    const float* Wg = (const float*)d_in[6];
    const float* bg = (const float*)d_in[7];
    float* out = (float*)d_out;

    bf16 *ph_, *pl_, *rh_, *rl_, *Whh, *Whl, *Wlh, *Wll, *Wgh, *Wgl;
    bf16 *Qh, *Ql, *Kh, *Kl;
    __half *E, *VT;
    float *Mg, *Sg, *sc;
    cudaGetSymbolAddress((void**)&ph_, g_ph);  cudaGetSymbolAddress((void**)&pl_, g_pl);
    cudaGetSymbolAddress((void**)&rh_, g_rh);  cudaGetSymbolAddress((void**)&rl_, g_rl);
    cudaGetSymbolAddress((void**)&Whh, g_Whh); cudaGetSymbolAddress((void**)&Whl, g_Whl);
    cudaGetSymbolAddress((void**)&Wlh, g_Wlh); cudaGetSymbolAddress((void**)&Wll, g_Wll);
    cudaGetSymbolAddress((void**)&Wgh, g_Wgh); cudaGetSymbolAddress((void**)&Wgl, g_Wgl);
    cudaGetSymbolAddress((void**)&Qh, g_Qh);   cudaGetSymbolAddress((void**)&Ql, g_Ql);
    cudaGetSymbolAddress((void**)&Kh, g_Kh);   cudaGetSymbolAddress((void**)&Kl, g_Kl);
    cudaGetSymbolAddress((void**)&VT, g_VT);
    cudaGetSymbolAddress((void**)&E, g_E);
    cudaGetSymbolAddress((void**)&Mg, g_M); cudaGetSymbolAddress((void**)&Sg, g_S);
    cudaGetSymbolAddress((void**)&sc, g_sc);

    cudaFuncSetAttribute(gemm_mma<1,3,0,3,2>, cudaFuncAttributeMaxDynamicSharedMemorySize, GSMEM3);
    cudaFuncSetAttribute(gemm_mma<4,3,0,3,2>, cudaFuncAttributeMaxDynamicSharedMemorySize, GSMEM3);
    cudaFuncSetAttribute(gemm_mma<2,3,0,3,2>, cudaFuncAttributeMaxDynamicSharedMemorySize, GSMEM3);
    cudaFuncSetAttribute(gemm_mma<3,1,1,3,3>, cudaFuncAttributeMaxDynamicSharedMemorySize, GSMEM1);

    const int nPD4 = NPTS * DIM / 4, nDD4 = DIM * DIM / 4;
    const int nTot = 2 * nPD4 + 3 * nDD4;
    split_all_kernel<<<(nTot + 255) / 256, 256>>>(
        (const float4*)p, (__nv_bfloat162*)ph_, (__nv_bfloat162*)pl_,
        (const float4*)r, (__nv_bfloat162*)rh_, (__nv_bfloat162*)rl_,
        (const float4*)Wh, (__nv_bfloat162*)Whh, (__nv_bfloat162*)Whl,
        (const float4*)Wl, (__nv_bfloat162*)Wlh, (__nv_bfloat162*)Wll,
        (const float4*)Wg, (__nv_bfloat162*)Wgh, (__nv_bfloat162*)Wgl);

    dim3 gproj(DIM/128, NPTS/128);
    gemm_mma<1,3,0,3,2><<<gproj, 128, GSMEM3>>>(ph_, pl_, Whh, Whl, DIM, DIM, bh, nullptr,
                                                nullptr, Qh, Ql, nullptr, nullptr);
    gemm_mma<1,3,0,3,2><<<gproj, 128, GSMEM3>>>(rh_, rl_, Wlh, Wll, DIM, DIM, bl, nullptr,
                                                nullptr, Kh, Kl, nullptr, nullptr);
    gemm_mma<4,3,0,3,2><<<gproj, 128, GSMEM3>>>(ph_, pl_, Wgh, Wgl, DIM, DIM, bg, nullptr,
                                                nullptr, (bf16*)VT, nullptr, nullptr, nullptr);

    dim3 gS(NPTS/128, NPTS/128);
    gemm_mma<2,3,0,3,2><<<gS, 128, GSMEM3>>>(Qh, Ql, Kh, Kl, DIM, NPTS, nullptr, nullptr,
                                             nullptr, (bf16*)E, nullptr, Mg, Sg);

    merge_kernel<<<NPTS/256, 256>>>(Mg, Sg, sc);
    norm_kernel<<<dim3(NPTS/512, 16), 256>>>((__half2*)E, sc);

    // PV at 3 CTAs/SM (NSTGT=3, 48KB/CTA)
    dim3 gpv(DIM/128, NPTS/128);
    gemm_mma<3,1,1,3,3><<<gpv, 128, GSMEM1>>>((const bf16*)E, nullptr, (const bf16*)VT, nullptr,
                                              NPTS, DIM, nullptr, p, out, nullptr, nullptr,
                                              nullptr, nullptr);
}

// round 16
// speedup vs baseline: 1.0504x; 1.0504x over previous
#include <cuda_runtime.h>
#include <cuda_bf16.h>
#include <cuda_fp16.h>
#include <cstdint>
#include <cstddef>

#define NPTS 8192
#define DIM  1024
typedef __nv_bfloat16 bf16;

#define AL __align__(256)
__device__ AL bf16 g_ph[(size_t)NPTS * DIM], g_pl[(size_t)NPTS * DIM];
__device__ AL bf16 g_rh[(size_t)NPTS * DIM], g_rl[(size_t)NPTS * DIM];
__device__ AL bf16 g_Whh[(size_t)DIM * DIM], g_Whl[(size_t)DIM * DIM];
__device__ AL bf16 g_Wlh[(size_t)DIM * DIM], g_Wll[(size_t)DIM * DIM];
__device__ AL bf16 g_Wgh[(size_t)DIM * DIM], g_Wgl[(size_t)DIM * DIM];
__device__ AL bf16 g_Qh[(size_t)NPTS * DIM], g_Ql[(size_t)NPTS * DIM];
__device__ AL bf16 g_Kh[(size_t)NPTS * DIM], g_Kl[(size_t)NPTS * DIM];
__device__ AL __half g_VT[(size_t)DIM * NPTS];
__device__ AL __half g_E[(size_t)NPTS * NPTS];
__device__ AL float g_M[64 * NPTS];
__device__ AL float g_S[64 * NPTS];
__device__ AL float g_sc[64 * NPTS];

__device__ __forceinline__ uint32_t smem_u32(const void* p) {
    uint32_t a;
    asm("{ .reg .u64 t; cvta.to.shared.u64 t, %1; cvt.u32.u64 %0, t; }" : "=r"(a) : "l"(p));
    return a;
}
__device__ __forceinline__ void cp16(uint32_t dst, const void* src) {
    asm volatile("cp.async.cg.shared.global [%0], [%1], 16;"
                 :: "r"(dst), "l"(__cvta_generic_to_global(src)) : "memory");
}
__device__ __forceinline__ void ldmx4(uint32_t* r, uint32_t addr) {
    asm volatile("ldmatrix.sync.aligned.m8n8.x4.shared.b16 {%0,%1,%2,%3}, [%4];"
                 : "=r"(r[0]), "=r"(r[1]), "=r"(r[2]), "=r"(r[3]) : "r"(addr));
}
__device__ __forceinline__ void mma_bf(float* c, const uint32_t* a, const uint32_t* b) {
    asm volatile("mma.sync.aligned.m16n8k16.row.col.f32.bf16.bf16.f32 "
                 "{%0,%1,%2,%3}, {%4,%5,%6,%7}, {%8,%9}, {%0,%1,%2,%3};"
                 : "+f"(c[0]), "+f"(c[1]), "+f"(c[2]), "+f"(c[3])
                 : "r"(a[0]), "r"(a[1]), "r"(a[2]), "r"(a[3]), "r"(b[0]), "r"(b[1]));
}
__device__ __forceinline__ void mma_hf(float* c, const uint32_t* a, const uint32_t* b) {
    asm volatile("mma.sync.aligned.m16n8k16.row.col.f32.f16.f16.f32 "
                 "{%0,%1,%2,%3}, {%4,%5,%6,%7}, {%8,%9}, {%0,%1,%2,%3};"
                 : "+f"(c[0]), "+f"(c[1]), "+f"(c[2]), "+f"(c[3])
                 : "r"(a[0]), "r"(a[1]), "r"(a[2]), "r"(a[3]), "r"(b[0]), "r"(b[1]));
}

// CTA tile 128x128, BK=32, cp.async pipeline (NSTGT stages). 4 warps, warp tile 64x64.
#define BK 32
#define GSMEM3 (3u * 32768u)
#define GSMEM1 (5u * 16384u)

__device__ __forceinline__ uint32_t swz(int row, int chunk) {
    return (uint32_t)(row * 64 + ((chunk ^ ((row >> 1) & 3)) << 4));
}

// MODE 0: bias+fp32 | 1: bias+bf16 hi/lo | 2: tile-softmax (fp16 E + M/S partials)
// MODE 3: residual fp32 | 4: bias + fp16 transposed (VT).  NPROD 3: hh+hl+lh | 1: hh.
template <int MODE, int NPROD, int HF, int NSTGT>
__global__ __launch_bounds__(128, 2) void gemm_mma(
    const bf16* __restrict__ Ahi, const bf16* __restrict__ Alo,
    const bf16* __restrict__ Bhi, const bf16* __restrict__ Blo,
    int Kd, int ldC, const float* __restrict__ bias, const float* __restrict__ P0,
    float* __restrict__ Cf, bf16* __restrict__ Chi, bf16* __restrict__ Clo,
    float* __restrict__ Mg, float* __restrict__ Sg)
{
    constexpr uint32_t STGB   = (NPROD == 1) ? 16384u : 32768u;
    constexpr uint32_t OF_ALO = 8192u;
    constexpr uint32_t OF_BHI = (NPROD == 1) ? 8192u : 16384u;
    constexpr uint32_t OF_BLO = 24576u;

    extern __shared__ char smraw[];
    const uint32_t sm0 = smem_u32(smraw);
    const int tid = threadIdx.x, lane = tid & 31, warp = tid >> 5;
    const int wm = warp >> 1, wn = warp & 1;           // 2x2 warp grid, 64x64 tiles
    const int row0 = blockIdx.y * 128, col0 = blockIdx.x * 128;

    uint32_t aoff[4][2], boff[4][2];
#pragma unroll
    for (int mi = 0; mi < 4; mi++)
#pragma unroll
        for (int ks = 0; ks < 2; ks++) {
            const int r = wm * 64 + mi * 16 + (lane & 15);
            aoff[mi][ks] = swz(r, ks * 2 + (lane >> 4));
        }
#pragma unroll
    for (int np = 0; np < 4; np++)
#pragma unroll
        for (int ks = 0; ks < 2; ks++) {
            const int r = wn * 64 + np * 16 + (lane & 7) + ((lane >> 4) & 1) * 8;
            boff[np][ks] = swz(r, ks * 2 + ((lane >> 3) & 1));
        }

    auto load_stage = [&](int kb, int st) {
        const int k0 = kb * BK;
        const uint32_t s = sm0 + (uint32_t)st * STGB;
#pragma unroll
        for (int i = 0; i < 4; i++) {
            const int id = i * 128 + tid;
            const int row = id >> 2, chunk = id & 3;
            const uint32_t d = swz(row, chunk);
            const size_t ga = (size_t)(row0 + row) * Kd + k0 + chunk * 8;
            const size_t gb = (size_t)(col0 + row) * Kd + k0 + chunk * 8;
            cp16(s + d, Ahi + ga);
            cp16(s + OF_BHI + d, Bhi + gb);
            if (NPROD == 3) {
                cp16(s + OF_ALO + d, Alo + ga);
                cp16(s + OF_BLO + d, Blo + gb);
            }
        }
    };

    float acc[4][8][4];
#pragma unroll
    for (int mi = 0; mi < 4; mi++)
#pragma unroll
        for (int ni = 0; ni < 8; ni++)
#pragma unroll
            for (int q = 0; q < 4; q++) acc[mi][ni][q] = 0.f;

    const int nkb = Kd / BK;
#pragma unroll
    for (int s = 0; s < NSTGT - 1; s++) {
        load_stage(s, s);
        asm volatile("cp.async.commit_group;" ::: "memory");
    }

    int st = 0, pf = NSTGT - 1;
    for (int kb = 0; kb < nkb; kb++) {
        asm volatile("cp.async.wait_group %0;" :: "n"(NSTGT - 2) : "memory");
        __syncthreads();
        if (kb + NSTGT - 1 < nkb) load_stage(kb + NSTGT - 1, pf);
        asm volatile("cp.async.commit_group;" ::: "memory");

        const uint32_t s = sm0 + (uint32_t)st * STGB;
#pragma unroll
        for (int ks = 0; ks < 2; ks++) {
            uint32_t ah[4][4], al[4][4], bh[8][2], bl[8][2];
#pragma unroll
            for (int mi = 0; mi < 4; mi++) {
                ldmx4(ah[mi], s + aoff[mi][ks]);
                if (NPROD == 3) ldmx4(al[mi], s + OF_ALO + aoff[mi][ks]);
            }
#pragma unroll
            for (int np = 0; np < 4; np++) {
                uint32_t t[4];
                ldmx4(t, s + OF_BHI + boff[np][ks]);
                bh[np*2][0] = t[0]; bh[np*2][1] = t[1];
                bh[np*2+1][0] = t[2]; bh[np*2+1][1] = t[3];
                if (NPROD == 3) {
                    ldmx4(t, s + OF_BLO + boff[np][ks]);
                    bl[np*2][0] = t[0]; bl[np*2][1] = t[1];
                    bl[np*2+1][0] = t[2]; bl[np*2+1][1] = t[3];
                }
            }
#pragma unroll
            for (int mi = 0; mi < 4; mi++)
#pragma unroll
                for (int ni = 0; ni < 8; ni++) {
                    if (HF) mma_hf(acc[mi][ni], ah[mi], bh[ni]);
                    else    mma_bf(acc[mi][ni], ah[mi], bh[ni]);
                }
            if (NPROD == 3) {
#pragma unroll
                for (int mi = 0; mi < 4; mi++)
#pragma unroll
                    for (int ni = 0; ni < 8; ni++)
                        mma_bf(acc[mi][ni], ah[mi], bl[ni]);
#pragma unroll
                for (int mi = 0; mi < 4; mi++)
#pragma unroll
                    for (int ni = 0; ni < 8; ni++)
                        mma_bf(acc[mi][ni], al[mi], bh[ni]);
            }
        }
        st = (st == NSTGT - 1) ? 0 : st + 1;
        pf = (pf == NSTGT - 1) ? 0 : pf + 1;
    }

    if (MODE == 2) {
        // Tile-local softmax epilogue; reuse stage smem (mainloop done).
        __syncthreads();
        float* Msm  = (float*)smraw;            // [2][128]
        float* Mfin = (float*)(smraw + 1024);   // [128]
        float* Ssm  = (float*)(smraw + 1536);   // [2][128]
#pragma unroll
        for (int ni = 0; ni < 8; ni++)
#pragma unroll
            for (int cc = 0; cc < 2; cc++) {
                float v = -1e30f;
#pragma unroll
                for (int mi = 0; mi < 4; mi++)
                    v = fmaxf(v, fmaxf(acc[mi][ni][cc], acc[mi][ni][2 + cc]));
                v = fmaxf(v, __shfl_xor_sync(0xffffffffu, v, 4));
                v = fmaxf(v, __shfl_xor_sync(0xffffffffu, v, 8));
                v = fmaxf(v, __shfl_xor_sync(0xffffffffu, v, 16));
                if (lane < 4) Msm[wm * 128 + wn * 64 + ni * 8 + lane * 2 + cc] = v;
            }
        __syncthreads();
        Mfin[tid] = fmaxf(Msm[tid], Msm[128 + tid]);
        __syncthreads();
        __half* Eo = (__half*)Chi;
        const float L2E = 1.4426950408889634f;
        float ss[8][2];
#pragma unroll
        for (int ni = 0; ni < 8; ni++) { ss[ni][0] = 0.f; ss[ni][1] = 0.f; }
#pragma unroll
        for (int mi = 0; mi < 4; mi++)
#pragma unroll
            for (int ni = 0; ni < 8; ni++) {
                const int cl = wn * 64 + ni * 8 + (lane & 3) * 2;
                const int c  = col0 + cl;
                const float M0 = Mfin[cl], M1 = Mfin[cl + 1];
#pragma unroll
                for (int h = 0; h < 2; h++) {
                    const int m = row0 + wm * 64 + mi * 16 + (lane >> 2) + h * 8;
                    float t0 = (acc[mi][ni][2 * h]     - M0) * L2E;
                    float t1 = (acc[mi][ni][2 * h + 1] - M1) * L2E;
                    __half2 ht = __floats2half2_rn(t0, t1);
                    uint32_t hin = *(uint32_t*)&ht, ho;
                    asm("ex2.approx.f16x2 %0, %1;" : "=r"(ho) : "r"(hin));
                    __half2 he = *(__half2*)&ho;
                    *(__half2*)&Eo[(size_t)m * ldC + c] = he;
                    float2 ef = __half22float2(he);
                    ss[ni][0] += ef.x; ss[ni][1] += ef.y;
                }
            }
#pragma unroll
        for (int ni = 0; ni < 8; ni++)
#pragma unroll
            for (int cc = 0; cc < 2; cc++) {
                float v = ss[ni][cc];
                v += __shfl_xor_sync(0xffffffffu, v, 4);
                v += __shfl_xor_sync(0xffffffffu, v, 8);
                v += __shfl_xor_sync(0xffffffffu, v, 16);
                if (lane < 4) Ssm[wm * 128 + wn * 64 + ni * 8 + lane * 2 + cc] = v;
            }
        __syncthreads();
        Mg[(size_t)blockIdx.y * ldC + col0 + tid] = Mfin[tid];
        Sg[(size_t)blockIdx.y * ldC + col0 + tid] = Ssm[tid] + Ssm[128 + tid];
        return;
    }

#pragma unroll
    for (int mi = 0; mi < 4; mi++)
#pragma unroll
        for (int ni = 0; ni < 8; ni++) {
            const int m0 = row0 + wm * 64 + mi * 16 + (lane >> 2);
            const int c  = col0 + wn * 64 + ni * 8 + (lane & 3) * 2;
#pragma unroll
            for (int h = 0; h < 2; h++) {
                const int m = m0 + h * 8;
                float v0 = acc[mi][ni][2 * h], v1 = acc[mi][ni][2 * h + 1];
                if (MODE == 0) {
                    float2* dst = (float2*)&Cf[(size_t)m * ldC + c];
                    *dst = make_float2(v0 + bias[c], v1 + bias[c + 1]);
                } else if (MODE == 3) {
                    const float2 pp = *(const float2*)&P0[(size_t)m * ldC + c];
                    float2* dst = (float2*)&Cf[(size_t)m * ldC + c];
                    *dst = make_float2(v0 + pp.x, v1 + pp.y);
                } else if (MODE == 4) {
                    __half* VTo = (__half*)Chi;
                    VTo[(size_t)c       * NPTS + m] = __float2half(v0 + bias[c]);
                    VTo[(size_t)(c + 1) * NPTS + m] = __float2half(v1 + bias[c + 1]);
                } else {  // MODE 1: bias + bf16 hi/lo split
                    v0 += bias[c]; v1 += bias[c + 1];
                    bf16 h0 = __float2bfloat16(v0), h1 = __float2bfloat16(v1);
                    *(__nv_bfloat162*)&Chi[(size_t)m * ldC + c] = __nv_bfloat162(h0, h1);
                    *(__nv_bfloat162*)&Clo[(size_t)m * ldC + c] =
                        __nv_bfloat162(__float2bfloat16(v0 - __bfloat162float(h0)),
                                       __float2bfloat16(v1 - __bfloat162float(h1)));
                }
            }
        }
}

// All five fp32->bf16 hi/lo splits in one launch (p, r, Wh, Wl, Wg).
__device__ __forceinline__ void split_one(const float4* x, __nv_bfloat162* hi,
                                          __nv_bfloat162* lo, int i) {
    float4 v = x[i];
    bf16 h0 = __float2bfloat16(v.x), h1 = __float2bfloat16(v.y);
    bf16 h2 = __float2bfloat16(v.z), h3 = __float2bfloat16(v.w);
    hi[2*i]   = __nv_bfloat162(h0, h1);
    hi[2*i+1] = __nv_bfloat162(h2, h3);
    lo[2*i]   = __nv_bfloat162(__float2bfloat16(v.x - __bfloat162float(h0)),
                               __float2bfloat16(v.y - __bfloat162float(h1)));
    lo[2*i+1] = __nv_bfloat162(__float2bfloat16(v.z - __bfloat162float(h2)),
                               __float2bfloat16(v.w - __bfloat162float(h3)));
}

__global__ __launch_bounds__(256) void split_all_kernel(
    const float4* p, __nv_bfloat162* ph, __nv_bfloat162* pl,
    const float4* r, __nv_bfloat162* rh, __nv_bfloat162* rl,
    const float4* wh, __nv_bfloat162* whh, __nv_bfloat162* whl,
    const float4* wl, __nv_bfloat162* wlh, __nv_bfloat162* wll,
    const float4* wg, __nv_bfloat162* wgh, __nv_bfloat162* wgl)
{
    const int nPD4 = NPTS * DIM / 4, nDD4 = DIM * DIM / 4;
    int i = blockIdx.x * 256 + threadIdx.x;
    if (i < nPD4) { split_one(p, ph, pl, i); return; }
    i -= nPD4;
    if (i < nPD4) { split_one(r, rh, rl, i); return; }
    i -= nPD4;
    if (i < nDD4) { split_one(wh, whh, whl, i); return; }
    i -= nDD4;
    if (i < nDD4) { split_one(wl, wlh, wll, i); return; }
    i -= nDD4;
    if (i < nDD4) split_one(wg, wgh, wgl, i);
}

// Combine 64 row-block partials -> per-column rescale factors sc[by][j]
__global__ __launch_bounds__(256) void merge_kernel(
    const float* __restrict__ Mg, const float* __restrict__ Sg, float* __restrict__ sc)
{
    const int j = blockIdx.x * 256 + threadIdx.x;
    float m = -1e30f;
#pragma unroll 8
    for (int by = 0; by < 64; by++) m = fmaxf(m, Mg[(size_t)by * NPTS + j]);
    float cs = 0.f;
#pragma unroll 8
    for (int by = 0; by < 64; by++)
        cs += Sg[(size_t)by * NPTS + j] * __expf(Mg[(size_t)by * NPTS + j] - m);
    const float rcv = 1.0f / cs;
#pragma unroll 8
    for (int by = 0; by < 64; by++)
        sc[(size_t)by * NPTS + j] = __expf(Mg[(size_t)by * NPTS + j] - m) * rcv;
}

// In-place: E[i,j] *= sc[i>>7][j]
__global__ __launch_bounds__(256) void norm_kernel(
    __half2* __restrict__ E, const float* __restrict__ sc)
{
    const int j2 = blockIdx.x * 256 + threadIdx.x;
    const int j = j2 * 2;
    const size_t i0 = (size_t)blockIdx.y * (NPTS / 16);
    for (int t = 0; t < NPTS / 16; t++) {
        const size_t i = i0 + t;
        const float* scr = sc + ((i >> 7) * (size_t)NPTS);
        const size_t idx = i * (NPTS / 2) + j2;
        float2 ef = __half22float2(E[idx]);
        E[idx] = __floats2half2_rn(ef.x * scr[j], ef.y * scr[j + 1]);
    }
}

extern "C" void kernel_launch(void* const* d_in, const int* in_sizes, int n_in,
                              void* d_out, int out_size)
{
    const float* p  = (const float*)d_in[0];
    const float* r  = (const float*)d_in[1];
    const float* Wh = (const float*)d_in[2];
    const float* bh = (const float*)d_in[3];
    const float* Wl = (const float*)d_in[4];
    const float* bl = (const float*)d_in[5];
    const float* Wg = (const float*)d_in[6];
    const float* bg = (const float*)d_in[7];
    float* out = (float*)d_out;

    bf16 *ph_, *pl_, *rh_, *rl_, *Whh, *Whl, *Wlh, *Wll, *Wgh, *Wgl;
    bf16 *Qh, *Ql, *Kh, *Kl;
    __half *E, *VT;
    float *Mg, *Sg, *sc;
    cudaGetSymbolAddress((void**)&ph_, g_ph);  cudaGetSymbolAddress((void**)&pl_, g_pl);
    cudaGetSymbolAddress((void**)&rh_, g_rh);  cudaGetSymbolAddress((void**)&rl_, g_rl);
    cudaGetSymbolAddress((void**)&Whh, g_Whh); cudaGetSymbolAddress((void**)&Whl, g_Whl);
    cudaGetSymbolAddress((void**)&Wlh, g_Wlh); cudaGetSymbolAddress((void**)&Wll, g_Wll);
    cudaGetSymbolAddress((void**)&Wgh, g_Wgh); cudaGetSymbolAddress((void**)&Wgl, g_Wgl);
    cudaGetSymbolAddress((void**)&Qh, g_Qh);   cudaGetSymbolAddress((void**)&Ql, g_Ql);
    cudaGetSymbolAddress((void**)&Kh, g_Kh);   cudaGetSymbolAddress((void**)&Kl, g_Kl);
    cudaGetSymbolAddress((void**)&VT, g_VT);
    cudaGetSymbolAddress((void**)&E, g_E);
    cudaGetSymbolAddress((void**)&Mg, g_M); cudaGetSymbolAddress((void**)&Sg, g_S);
    cudaGetSymbolAddress((void**)&sc, g_sc);

    cudaFuncSetAttribute(gemm_mma<1,3,0,3>, cudaFuncAttributeMaxDynamicSharedMemorySize, GSMEM3);
    cudaFuncSetAttribute(gemm_mma<4,3,0,3>, cudaFuncAttributeMaxDynamicSharedMemorySize, GSMEM3);
    cudaFuncSetAttribute(gemm_mma<2,3,0,3>, cudaFuncAttributeMaxDynamicSharedMemorySize, GSMEM3);
    cudaFuncSetAttribute(gemm_mma<3,1,1,5>, cudaFuncAttributeMaxDynamicSharedMemorySize, GSMEM1);

    const int nPD4 = NPTS * DIM / 4, nDD4 = DIM * DIM / 4;
    const int nTot = 2 * nPD4 + 3 * nDD4;
    split_all_kernel<<<(nTot + 255) / 256, 256>>>(
        (const float4*)p, (__nv_bfloat162*)ph_, (__nv_bfloat162*)pl_,
        (const float4*)r, (__nv_bfloat162*)rh_, (__nv_bfloat162*)rl_,
        (const float4*)Wh, (__nv_bfloat162*)Whh, (__nv_bfloat162*)Whl,
        (const float4*)Wl, (__nv_bfloat162*)Wlh, (__nv_bfloat162*)Wll,
        (const float4*)Wg, (__nv_bfloat162*)Wgh, (__nv_bfloat162*)Wgl);

    dim3 gproj(DIM/128, NPTS/128);
    gemm_mma<1,3,0,3><<<gproj, 128, GSMEM3>>>(ph_, pl_, Whh, Whl, DIM, DIM, bh, nullptr,
                                              nullptr, Qh, Ql, nullptr, nullptr);
    gemm_mma<1,3,0,3><<<gproj, 128, GSMEM3>>>(rh_, rl_, Wlh, Wll, DIM, DIM, bl, nullptr,
                                              nullptr, Kh, Kl, nullptr, nullptr);
    gemm_mma<4,3,0,3><<<gproj, 128, GSMEM3>>>(ph_, pl_, Wgh, Wgl, DIM, DIM, bg, nullptr,
                                              nullptr, (bf16*)VT, nullptr, nullptr, nullptr);

    dim3 gS(NPTS/128, NPTS/128);
    gemm_mma<2,3,0,3><<<gS, 128, GSMEM3>>>(Qh, Ql, Kh, Kl, DIM, NPTS, nullptr, nullptr,
                                           nullptr, (bf16*)E, nullptr, Mg, Sg);

    merge_kernel<<<NPTS/256, 256>>>(Mg, Sg, sc);
    norm_kernel<<<dim3(NPTS/512, 16), 256>>>((__half2*)E, sc);

    // PV: NSTGT=5, 2 CTAs/SM (register-capped; 3 CTAs/SM spills — measured R13)
    dim3 gpv(DIM/128, NPTS/128);
    gemm_mma<3,1,1,5><<<gpv, 128, GSMEM1>>>((const bf16*)E, nullptr, (const bf16*)VT, nullptr,
                                            NPTS, DIM, nullptr, p, out, nullptr, nullptr,
                                            nullptr, nullptr);
}

// round 17
// speedup vs baseline: 1.0654x; 1.0142x over previous
#include <cuda_runtime.h>
#include <cuda_bf16.h>
#include <cuda_fp16.h>
#include <cstdint>
#include <cstddef>

#define NPTS 8192
#define DIM  1024
typedef __nv_bfloat16 bf16;

#define AL __align__(256)
__device__ AL bf16 g_ph[(size_t)NPTS * DIM], g_pl[(size_t)NPTS * DIM];
__device__ AL bf16 g_rh[(size_t)NPTS * DIM], g_rl[(size_t)NPTS * DIM];
__device__ AL bf16 g_Whh[(size_t)DIM * DIM], g_Whl[(size_t)DIM * DIM];
__device__ AL bf16 g_Wlh[(size_t)DIM * DIM], g_Wll[(size_t)DIM * DIM];
__device__ AL bf16 g_Wgh[(size_t)DIM * DIM], g_Wgl[(size_t)DIM * DIM];
__device__ AL bf16 g_Qh[(size_t)NPTS * DIM], g_Ql[(size_t)NPTS * DIM];
__device__ AL bf16 g_Kh[(size_t)NPTS * DIM], g_Kl[(size_t)NPTS * DIM];
__device__ AL __half g_VT[(size_t)DIM * NPTS];
__device__ AL __half g_E[(size_t)NPTS * NPTS];
__device__ AL float g_M[64 * NPTS];
__device__ AL float g_S[64 * NPTS];
__device__ AL float g_sc[64 * NPTS];

__device__ __forceinline__ uint32_t smem_u32(const void* p) {
    uint32_t a;
    asm("{ .reg .u64 t; cvta.to.shared.u64 t, %1; cvt.u32.u64 %0, t; }" : "=r"(a) : "l"(p));
    return a;
}
__device__ __forceinline__ void cp16(uint32_t dst, const void* src) {
    asm volatile("cp.async.cg.shared.global [%0], [%1], 16;"
                 :: "r"(dst), "l"(__cvta_generic_to_global(src)) : "memory");
}
__device__ __forceinline__ void ldmx4(uint32_t* r, uint32_t addr) {
    asm volatile("ldmatrix.sync.aligned.m8n8.x4.shared.b16 {%0,%1,%2,%3}, [%4];"
                 : "=r"(r[0]), "=r"(r[1]), "=r"(r[2]), "=r"(r[3]) : "r"(addr));
}
__device__ __forceinline__ void mma_bf(float* c, const uint32_t* a, const uint32_t* b) {
    asm volatile("mma.sync.aligned.m16n8k16.row.col.f32.bf16.bf16.f32 "
                 "{%0,%1,%2,%3}, {%4,%5,%6,%7}, {%8,%9}, {%0,%1,%2,%3};"
                 : "+f"(c[0]), "+f"(c[1]), "+f"(c[2]), "+f"(c[3])
                 : "r"(a[0]), "r"(a[1]), "r"(a[2]), "r"(a[3]), "r"(b[0]), "r"(b[1]));
}
__device__ __forceinline__ void mma_hf(float* c, const uint32_t* a, const uint32_t* b) {
    asm volatile("mma.sync.aligned.m16n8k16.row.col.f32.f16.f16.f32 "
                 "{%0,%1,%2,%3}, {%4,%5,%6,%7}, {%8,%9}, {%0,%1,%2,%3};"
                 : "+f"(c[0]), "+f"(c[1]), "+f"(c[2]), "+f"(c[3])
                 : "r"(a[0]), "r"(a[1]), "r"(a[2]), "r"(a[3]), "r"(b[0]), "r"(b[1]));
}

// CTA tile 128x128, BK=32, cp.async pipeline (NSTGT stages). 4 warps, warp tile 64x64.
#define BK 32
#define GSMEM3 (3u * 32768u)
#define GSMEM1 (5u * 16384u)

__device__ __forceinline__ uint32_t swz(int row, int chunk) {
    return (uint32_t)(row * 64 + ((chunk ^ ((row >> 1) & 3)) << 4));
}

// ---------------------------------------------------------------------------
// Merged Q/K/V projection: one launch, grid.z in {0=Q, 1=K, 2=V}.
// Mainloop = proven NPROD=3 / NSTGT=3 loop. Epilogue: z<2 -> bias + bf16 hi/lo;
// z==2 -> bias + fp16 transposed VT.
// ---------------------------------------------------------------------------
__global__ __launch_bounds__(128, 2) void proj_all(
    const float* __restrict__ bh, const float* __restrict__ bl,
    const float* __restrict__ bg)
{
    constexpr uint32_t STGB = 32768u;
    constexpr uint32_t OF_ALO = 8192u, OF_BHI = 16384u, OF_BLO = 24576u;
    constexpr int NSTGT = 3;

    extern __shared__ char smraw[];
    const uint32_t sm0 = smem_u32(smraw);
    const int tid = threadIdx.x, lane = tid & 31, warp = tid >> 5;
    const int wm = warp >> 1, wn = warp & 1;
    const int row0 = blockIdx.y * 128, col0 = blockIdx.x * 128;
    const int z = blockIdx.z;

    const bf16* Ahi = (z == 1) ? g_rh : g_ph;
    const bf16* Alo = (z == 1) ? g_rl : g_pl;
    const bf16* Bhi = (z == 0) ? g_Whh : (z == 1) ? g_Wlh : g_Wgh;
    const bf16* Blo = (z == 0) ? g_Whl : (z == 1) ? g_Wll : g_Wgl;
    const float* bias = (z == 0) ? bh : (z == 1) ? bl : bg;

    uint32_t aoff[4][2], boff[4][2];
#pragma unroll
    for (int mi = 0; mi < 4; mi++)
#pragma unroll
        for (int ks = 0; ks < 2; ks++) {
            const int r = wm * 64 + mi * 16 + (lane & 15);
            aoff[mi][ks] = swz(r, ks * 2 + (lane >> 4));
        }
#pragma unroll
    for (int np = 0; np < 4; np++)
#pragma unroll
        for (int ks = 0; ks < 2; ks++) {
            const int r = wn * 64 + np * 16 + (lane & 7) + ((lane >> 4) & 1) * 8;
            boff[np][ks] = swz(r, ks * 2 + ((lane >> 3) & 1));
        }

    auto load_stage = [&](int kb, int st) {
        const int k0 = kb * BK;
        const uint32_t s = sm0 + (uint32_t)st * STGB;
#pragma unroll
        for (int i = 0; i < 4; i++) {
            const int id = i * 128 + tid;
            const int row = id >> 2, chunk = id & 3;
            const uint32_t d = swz(row, chunk);
            const size_t ga = (size_t)(row0 + row) * DIM + k0 + chunk * 8;
            const size_t gb = (size_t)(col0 + row) * DIM + k0 + chunk * 8;
            cp16(s + d, Ahi + ga);
            cp16(s + OF_BHI + d, Bhi + gb);
            cp16(s + OF_ALO + d, Alo + ga);
            cp16(s + OF_BLO + d, Blo + gb);
        }
    };

    float acc[4][8][4];
#pragma unroll
    for (int mi = 0; mi < 4; mi++)
#pragma unroll
        for (int ni = 0; ni < 8; ni++)
#pragma unroll
            for (int q = 0; q < 4; q++) acc[mi][ni][q] = 0.f;

    const int nkb = DIM / BK;
#pragma unroll
    for (int s = 0; s < NSTGT - 1; s++) {
        load_stage(s, s);
        asm volatile("cp.async.commit_group;" ::: "memory");
    }

    int st = 0, pf = NSTGT - 1;
    for (int kb = 0; kb < nkb; kb++) {
        asm volatile("cp.async.wait_group %0;" :: "n"(NSTGT - 2) : "memory");
        __syncthreads();
        if (kb + NSTGT - 1 < nkb) load_stage(kb + NSTGT - 1, pf);
        asm volatile("cp.async.commit_group;" ::: "memory");

        const uint32_t s = sm0 + (uint32_t)st * STGB;
#pragma unroll
        for (int ks = 0; ks < 2; ks++) {
            uint32_t ah[4][4], al[4][4], bhf[8][2], blf[8][2];
#pragma unroll
            for (int mi = 0; mi < 4; mi++) {
                ldmx4(ah[mi], s + aoff[mi][ks]);
                ldmx4(al[mi], s + OF_ALO + aoff[mi][ks]);
            }
#pragma unroll
            for (int np = 0; np < 4; np++) {
                uint32_t t[4];
                ldmx4(t, s + OF_BHI + boff[np][ks]);
                bhf[np*2][0] = t[0]; bhf[np*2][1] = t[1];
                bhf[np*2+1][0] = t[2]; bhf[np*2+1][1] = t[3];
                ldmx4(t, s + OF_BLO + boff[np][ks]);
                blf[np*2][0] = t[0]; blf[np*2][1] = t[1];
                blf[np*2+1][0] = t[2]; blf[np*2+1][1] = t[3];
            }
#pragma unroll
            for (int mi = 0; mi < 4; mi++)
#pragma unroll
                for (int ni = 0; ni < 8; ni++)
                    mma_bf(acc[mi][ni], ah[mi], bhf[ni]);
#pragma unroll
            for (int mi = 0; mi < 4; mi++)
#pragma unroll
                for (int ni = 0; ni < 8; ni++)
                    mma_bf(acc[mi][ni], ah[mi], blf[ni]);
#pragma unroll
            for (int mi = 0; mi < 4; mi++)
#pragma unroll
                for (int ni = 0; ni < 8; ni++)
                    mma_bf(acc[mi][ni], al[mi], bhf[ni]);
        }
        st = (st == NSTGT - 1) ? 0 : st + 1;
        pf = (pf == NSTGT - 1) ? 0 : pf + 1;
    }

    bf16* Chi = (z == 0) ? g_Qh : g_Kh;
    bf16* Clo = (z == 0) ? g_Ql : g_Kl;
#pragma unroll
    for (int mi = 0; mi < 4; mi++)
#pragma unroll
        for (int ni = 0; ni < 8; ni++) {
            const int m0 = row0 + wm * 64 + mi * 16 + (lane >> 2);
            const int c  = col0 + wn * 64 + ni * 8 + (lane & 3) * 2;
#pragma unroll
            for (int h = 0; h < 2; h++) {
                const int m = m0 + h * 8;
                float v0 = acc[mi][ni][2 * h] + bias[c];
                float v1 = acc[mi][ni][2 * h + 1] + bias[c + 1];
                if (z == 2) {
                    g_VT[(size_t)c       * NPTS + m] = __float2half(v0);
                    g_VT[(size_t)(c + 1) * NPTS + m] = __float2half(v1);
                } else {
                    bf16 h0 = __float2bfloat16(v0), h1 = __float2bfloat16(v1);
                    *(__nv_bfloat162*)&Chi[(size_t)m * DIM + c] = __nv_bfloat162(h0, h1);
                    *(__nv_bfloat162*)&Clo[(size_t)m * DIM + c] =
                        __nv_bfloat162(__float2bfloat16(v0 - __bfloat162float(h0)),
                                       __float2bfloat16(v1 - __bfloat162float(h1)));
                }
            }
        }
}

// MODE 2: tile-softmax (fp16 E + M/S partials) | 3: residual fp32.
// NPROD 3: hh+hl+lh | 1: hh.  HF: fp16 operands.
template <int MODE, int NPROD, int HF, int NSTGT>
__global__ __launch_bounds__(128, 2) void gemm_mma(
    const bf16* __restrict__ Ahi, const bf16* __restrict__ Alo,
    const bf16* __restrict__ Bhi, const bf16* __restrict__ Blo,
    int Kd, int ldC, const float* __restrict__ bias, const float* __restrict__ P0,
    float* __restrict__ Cf, bf16* __restrict__ Chi, bf16* __restrict__ Clo,
    float* __restrict__ Mg, float* __restrict__ Sg)
{
    constexpr uint32_t STGB   = (NPROD == 1) ? 16384u : 32768u;
    constexpr uint32_t OF_ALO = 8192u;
    constexpr uint32_t OF_BHI = (NPROD == 1) ? 8192u : 16384u;
    constexpr uint32_t OF_BLO = 24576u;

    extern __shared__ char smraw[];
    const uint32_t sm0 = smem_u32(smraw);
    const int tid = threadIdx.x, lane = tid & 31, warp = tid >> 5;
    const int wm = warp >> 1, wn = warp & 1;
    const int row0 = blockIdx.y * 128, col0 = blockIdx.x * 128;

    uint32_t aoff[4][2], boff[4][2];
#pragma unroll
    for (int mi = 0; mi < 4; mi++)
#pragma unroll
        for (int ks = 0; ks < 2; ks++) {
            const int r = wm * 64 + mi * 16 + (lane & 15);
            aoff[mi][ks] = swz(r, ks * 2 + (lane >> 4));
        }
#pragma unroll
    for (int np = 0; np < 4; np++)
#pragma unroll
        for (int ks = 0; ks < 2; ks++) {
            const int r = wn * 64 + np * 16 + (lane & 7) + ((lane >> 4) & 1) * 8;
            boff[np][ks] = swz(r, ks * 2 + ((lane >> 3) & 1));
        }

    auto load_stage = [&](int kb, int st) {
        const int k0 = kb * BK;
        const uint32_t s = sm0 + (uint32_t)st * STGB;
#pragma unroll
        for (int i = 0; i < 4; i++) {
            const int id = i * 128 + tid;
            const int row = id >> 2, chunk = id & 3;
            const uint32_t d = swz(row, chunk);
            const size_t ga = (size_t)(row0 + row) * Kd + k0 + chunk * 8;
            const size_t gb = (size_t)(col0 + row) * Kd + k0 + chunk * 8;
            cp16(s + d, Ahi + ga);
            cp16(s + OF_BHI + d, Bhi + gb);
            if (NPROD == 3) {
                cp16(s + OF_ALO + d, Alo + ga);
                cp16(s + OF_BLO + d, Blo + gb);
            }
        }
    };

    float acc[4][8][4];
#pragma unroll
    for (int mi = 0; mi < 4; mi++)
#pragma unroll
        for (int ni = 0; ni < 8; ni++)
#pragma unroll
            for (int q = 0; q < 4; q++) acc[mi][ni][q] = 0.f;

    const int nkb = Kd / BK;
#pragma unroll
    for (int s = 0; s < NSTGT - 1; s++) {
        load_stage(s, s);
        asm volatile("cp.async.commit_group;" ::: "memory");
    }

    int st = 0, pf = NSTGT - 1;
    for (int kb = 0; kb < nkb; kb++) {
        asm volatile("cp.async.wait_group %0;" :: "n"(NSTGT - 2) : "memory");
        __syncthreads();
        if (kb + NSTGT - 1 < nkb) load_stage(kb + NSTGT - 1, pf);
        asm volatile("cp.async.commit_group;" ::: "memory");

        const uint32_t s = sm0 + (uint32_t)st * STGB;
#pragma unroll
        for (int ks = 0; ks < 2; ks++) {
            uint32_t ah[4][4], al[4][4], bh[8][2], bl[8][2];
#pragma unroll
            for (int mi = 0; mi < 4; mi++) {
                ldmx4(ah[mi], s + aoff[mi][ks]);
                if (NPROD == 3) ldmx4(al[mi], s + OF_ALO + aoff[mi][ks]);
            }
#pragma unroll
            for (int np = 0; np < 4; np++) {
                uint32_t t[4];
                ldmx4(t, s + OF_BHI + boff[np][ks]);
                bh[np*2][0] = t[0]; bh[np*2][1] = t[1];
                bh[np*2+1][0] = t[2]; bh[np*2+1][1] = t[3];
                if (NPROD == 3) {
                    ldmx4(t, s + OF_BLO + boff[np][ks]);
                    bl[np*2][0] = t[0]; bl[np*2][1] = t[1];
                    bl[np*2+1][0] = t[2]; bl[np*2+1][1] = t[3];
                }
            }
#pragma unroll
            for (int mi = 0; mi < 4; mi++)
#pragma unroll
                for (int ni = 0; ni < 8; ni++) {
                    if (HF) mma_hf(acc[mi][ni], ah[mi], bh[ni]);
                    else    mma_bf(acc[mi][ni], ah[mi], bh[ni]);
                }
            if (NPROD == 3) {
#pragma unroll
                for (int mi = 0; mi < 4; mi++)
#pragma unroll
                    for (int ni = 0; ni < 8; ni++)
                        mma_bf(acc[mi][ni], ah[mi], bl[ni]);
#pragma unroll
                for (int mi = 0; mi < 4; mi++)
#pragma unroll
                    for (int ni = 0; ni < 8; ni++)
                        mma_bf(acc[mi][ni], al[mi], bh[ni]);
            }
        }
        st = (st == NSTGT - 1) ? 0 : st + 1;
        pf = (pf == NSTGT - 1) ? 0 : pf + 1;
    }

    if (MODE == 2) {
        __syncthreads();
        float* Msm  = (float*)smraw;
        float* Mfin = (float*)(smraw + 1024);
        float* Ssm  = (float*)(smraw + 1536);
#pragma unroll
        for (int ni = 0; ni < 8; ni++)
#pragma unroll
            for (int cc = 0; cc < 2; cc++) {
                float v = -1e30f;
#pragma unroll
                for (int mi = 0; mi < 4; mi++)
                    v = fmaxf(v, fmaxf(acc[mi][ni][cc], acc[mi][ni][2 + cc]));
                v = fmaxf(v, __shfl_xor_sync(0xffffffffu, v, 4));
                v = fmaxf(v, __shfl_xor_sync(0xffffffffu, v, 8));
                v = fmaxf(v, __shfl_xor_sync(0xffffffffu, v, 16));
                if (lane < 4) Msm[wm * 128 + wn * 64 + ni * 8 + lane * 2 + cc] = v;
            }
        __syncthreads();
        Mfin[tid] = fmaxf(Msm[tid], Msm[128 + tid]);
        __syncthreads();
        __half* Eo = (__half*)Chi;
        const float L2E = 1.4426950408889634f;
        float ss[8][2];
#pragma unroll
        for (int ni = 0; ni < 8; ni++) { ss[ni][0] = 0.f; ss[ni][1] = 0.f; }
#pragma unroll
        for (int mi = 0; mi < 4; mi++)
#pragma unroll
            for (int ni = 0; ni < 8; ni++) {
                const int cl = wn * 64 + ni * 8 + (lane & 3) * 2;
                const int c  = col0 + cl;
                const float M0 = Mfin[cl], M1 = Mfin[cl + 1];
#pragma unroll
                for (int h = 0; h < 2; h++) {
                    const int m = row0 + wm * 64 + mi * 16 + (lane >> 2) + h * 8;
                    float t0 = (acc[mi][ni][2 * h]     - M0) * L2E;
                    float t1 = (acc[mi][ni][2 * h + 1] - M1) * L2E;
                    __half2 ht = __floats2half2_rn(t0, t1);
                    uint32_t hin = *(uint32_t*)&ht, ho;
                    asm("ex2.approx.f16x2 %0, %1;" : "=r"(ho) : "r"(hin));
                    __half2 he = *(__half2*)&ho;
                    *(__half2*)&Eo[(size_t)m * ldC + c] = he;
                    float2 ef = __half22float2(he);
                    ss[ni][0] += ef.x; ss[ni][1] += ef.y;
                }
            }
#pragma unroll
        for (int ni = 0; ni < 8; ni++)
#pragma unroll
            for (int cc = 0; cc < 2; cc++) {
                float v = ss[ni][cc];
                v += __shfl_xor_sync(0xffffffffu, v, 4);
                v += __shfl_xor_sync(0xffffffffu, v, 8);
                v += __shfl_xor_sync(0xffffffffu, v, 16);
                if (lane < 4) Ssm[wm * 128 + wn * 64 + ni * 8 + lane * 2 + cc] = v;
            }
        __syncthreads();
        Mg[(size_t)blockIdx.y * ldC + col0 + tid] = Mfin[tid];
        Sg[(size_t)blockIdx.y * ldC + col0 + tid] = Ssm[tid] + Ssm[128 + tid];
        return;
    }

    // MODE 3: residual fp32
#pragma unroll
    for (int mi = 0; mi < 4; mi++)
#pragma unroll
        for (int ni = 0; ni < 8; ni++) {
            const int m0 = row0 + wm * 64 + mi * 16 + (lane >> 2);
            const int c  = col0 + wn * 64 + ni * 8 + (lane & 3) * 2;
#pragma unroll
            for (int h = 0; h < 2; h++) {
                const int m = m0 + h * 8;
                const float2 pp = *(const float2*)&P0[(size_t)m * ldC + c];
                float2* dst = (float2*)&Cf[(size_t)m * ldC + c];
                *dst = make_float2(acc[mi][ni][2 * h] + pp.x,
                                   acc[mi][ni][2 * h + 1] + pp.y);
            }
        }
}

// All five fp32->bf16 hi/lo splits in one launch (p, r, Wh, Wl, Wg).
__device__ __forceinline__ void split_one(const float4* x, __nv_bfloat162* hi,
                                          __nv_bfloat162* lo, int i) {
    float4 v = x[i];
    bf16 h0 = __float2bfloat16(v.x), h1 = __float2bfloat16(v.y);
    bf16 h2 = __float2bfloat16(v.z), h3 = __float2bfloat16(v.w);
    hi[2*i]   = __nv_bfloat162(h0, h1);
    hi[2*i+1] = __nv_bfloat162(h2, h3);
    lo[2*i]   = __nv_bfloat162(__float2bfloat16(v.x - __bfloat162float(h0)),
                               __float2bfloat16(v.y - __bfloat162float(h1)));
    lo[2*i+1] = __nv_bfloat162(__float2bfloat16(v.z - __bfloat162float(h2)),
                               __float2bfloat16(v.w - __bfloat162float(h3)));
}

__global__ __launch_bounds__(256) void split_all_kernel(
    const float4* p, const float4* r, const float4* wh, const float4* wl,
    const float4* wg)
{
    const int nPD4 = NPTS * DIM / 4, nDD4 = DIM * DIM / 4;
    int i = blockIdx.x * 256 + threadIdx.x;
    if (i < nPD4) { split_one(p, (__nv_bfloat162*)g_ph, (__nv_bfloat162*)g_pl, i); return; }
    i -= nPD4;
    if (i < nPD4) { split_one(r, (__nv_bfloat162*)g_rh, (__nv_bfloat162*)g_rl, i); return; }
    i -= nPD4;
    if (i < nDD4) { split_one(wh, (__nv_bfloat162*)g_Whh, (__nv_bfloat162*)g_Whl, i); return; }
    i -= nDD4;
    if (i < nDD4) { split_one(wl, (__nv_bfloat162*)g_Wlh, (__nv_bfloat162*)g_Wll, i); return; }
    i -= nDD4;
    if (i < nDD4) split_one(wg, (__nv_bfloat162*)g_Wgh, (__nv_bfloat162*)g_Wgl, i);
}

// Combine 64 row-block partials -> per-column rescale factors sc[by][j]
__global__ __launch_bounds__(256) void merge_kernel(
    const float* __restrict__ Mg, const float* __restrict__ Sg, float* __restrict__ sc)
{
    const int j = blockIdx.x * 256 + threadIdx.x;
    float m = -1e30f;
#pragma unroll 8
    for (int by = 0; by < 64; by++) m = fmaxf(m, Mg[(size_t)by * NPTS + j]);
    float cs = 0.f;
#pragma unroll 8
    for (int by = 0; by < 64; by++)
        cs += Sg[(size_t)by * NPTS + j] * __expf(Mg[(size_t)by * NPTS + j] - m);
    const float rcv = 1.0f / cs;
#pragma unroll 8
    for (int by = 0; by < 64; by++)
        sc[(size_t)by * NPTS + j] = __expf(Mg[(size_t)by * NPTS + j] - m) * rcv;
}

// In-place: E[i,j] *= sc[i>>7][j]
__global__ __launch_bounds__(256) void norm_kernel(
    __half2* __restrict__ E, const float* __restrict__ sc)
{
    const int j2 = blockIdx.x * 256 + threadIdx.x;
    const int j = j2 * 2;
    const size_t i0 = (size_t)blockIdx.y * (NPTS / 16);
    for (int t = 0; t < NPTS / 16; t++) {
        const size_t i = i0 + t;
        const float* scr = sc + ((i >> 7) * (size_t)NPTS);
        const size_t idx = i * (NPTS / 2) + j2;
        float2 ef = __half22float2(E[idx]);
        E[idx] = __floats2half2_rn(ef.x * scr[j], ef.y * scr[j + 1]);
    }
}

extern "C" void kernel_launch(void* const* d_in, const int* in_sizes, int n_in,
                              void* d_out, int out_size)
{
    const float* p  = (const float*)d_in[0];
    const float* r  = (const float*)d_in[1];
    const float* Wh = (const float*)d_in[2];
    const float* bh = (const float*)d_in[3];
    const float* Wl = (const float*)d_in[4];
    const float* bl = (const float*)d_in[5];
    const float* Wg = (const float*)d_in[6];
    const float* bg = (const float*)d_in[7];
    float* out = (float*)d_out;

    bf16 *Qh, *Ql, *Kh, *Kl;
    __half *E, *VT;
    float *Mg, *Sg, *sc;
    cudaGetSymbolAddress((void**)&Qh, g_Qh);   cudaGetSymbolAddress((void**)&Ql, g_Ql);
    cudaGetSymbolAddress((void**)&Kh, g_Kh);   cudaGetSymbolAddress((void**)&Kl, g_Kl);
    cudaGetSymbolAddress((void**)&VT, g_VT);
    cudaGetSymbolAddress((void**)&E, g_E);
    cudaGetSymbolAddress((void**)&Mg, g_M); cudaGetSymbolAddress((void**)&Sg, g_S);
    cudaGetSymbolAddress((void**)&sc, g_sc);

    cudaFuncSetAttribute(proj_all, cudaFuncAttributeMaxDynamicSharedMemorySize, GSMEM3);
    cudaFuncSetAttribute(gemm_mma<2,3,0,3>, cudaFuncAttributeMaxDynamicSharedMemorySize, GSMEM3);
    cudaFuncSetAttribute(gemm_mma<3,1,1,5>, cudaFuncAttributeMaxDynamicSharedMemorySize, GSMEM1);

    const int nPD4 = NPTS * DIM / 4, nDD4 = DIM * DIM / 4;
    const int nTot = 2 * nPD4 + 3 * nDD4;
    split_all_kernel<<<(nTot + 255) / 256, 256>>>(
        (const float4*)p, (const float4*)r, (const float4*)Wh,
        (const float4*)Wl, (const float4*)Wg);

    // Q, K, V projections in ONE launch (grid.z selects; scheduler backfills the tail)
    dim3 gproj(DIM/128, NPTS/128, 3);
    proj_all<<<gproj, 128, GSMEM3>>>(bh, bl, bg);

    dim3 gS(NPTS/128, NPTS/128);
    gemm_mma<2,3,0,3><<<gS, 128, GSMEM3>>>(Qh, Ql, Kh, Kl, DIM, NPTS, nullptr, nullptr,
                                           nullptr, (bf16*)E, nullptr, Mg, Sg);

    merge_kernel<<<NPTS/256, 256>>>(Mg, Sg, sc);
    norm_kernel<<<dim3(NPTS/512, 16), 256>>>((__half2*)E, sc);

    // PV: NSTGT=5, 2 CTAs/SM (register-capped; 3 CTAs/SM spills — measured R13)
    dim3 gpv(DIM/128, NPTS/128);
    gemm_mma<3,1,1,5><<<gpv, 128, GSMEM1>>>((const bf16*)E, nullptr, (const bf16*)VT, nullptr,
                                            NPTS, DIM, nullptr, p, out, nullptr, nullptr,
                                            nullptr, nullptr);
}